// round 3
// baseline (speedup 1.0000x reference)
#include <cuda_runtime.h>
#include <cstdint>
#include <math.h>

// Problem constants (fixed by the reference setup_inputs)
#define NE    1024            // codebook size
#define ED    256             // embedding dim (= channels)
#define HW    4096            // 64*64
#define NROWS 65536           // 16 * HW
#define CHW   (ED * HW)       // 1048576
#define OUTZ  16777216        // 16 * CHW  (z_q_out element count)

// ---------------- scratch (device globals; no allocation allowed) ----------
__device__ __align__(16) float g_embT[ED * NE];   // [c][code] transposed table
__device__ float  g_e2[NE];                       // ||e_j||^2
__device__ __align__(16) int   g_idx[NROWS];      // argmin indices
__device__ int    g_counts[NE];                   // usage histogram
__device__ float  g_partial[1024];                // per-block loss partials

// ---------------- init: zero the histogram -------------------------------
__global__ void init_kernel() {
    int t = threadIdx.x;
    if (t < NE) g_counts[t] = 0;
}

// ---------------- prep: transpose embedding + squared norms ---------------
__global__ void prep_kernel(const float* __restrict__ emb) {
    int code = blockIdx.x;      // 0..1023
    int c    = threadIdx.x;     // 0..255
    float v = emb[code * ED + c];
    g_embT[c * NE + code] = v;
    float s = v * v;
    #pragma unroll
    for (int off = 16; off; off >>= 1)
        s += __shfl_xor_sync(0xffffffffu, s, off);
    __shared__ float red[8];
    if ((c & 31) == 0) red[c >> 5] = s;
    __syncthreads();
    if (c == 0) {
        float t = 0.f;
        #pragma unroll
        for (int i = 0; i < 8; i++) t += red[i];
        g_e2[code] = t;
    }
}

// ---------------- fused GEMM + argmin -------------------------------------
// Tile: 128 rows x 128 codes per block, K chunked by 32. 256 threads,
// 8x8 register tile each. z is channel-major => k-major loads coalesce.
// Distance is computed EXACTLY like the jax reference:
//   d = fl( fl(z2 + e2_j) - fl(2*dot_j) )
// so that ulp(256)-level quantization and argmin-first tie-breaks match.
#define TM 128
#define TN 128
#define TK 32

__global__ __launch_bounds__(256, 2)
void argmin_kernel(const float* __restrict__ z) {
    __shared__ float zs[TK][TM];   // [k][row]
    __shared__ float es[TK][TN];   // [k][code], granule-swizzled
    __shared__ float e2s[TN];

    const int tid = threadIdx.x;
    const int tx = tid & 15;       // code group
    const int ty = tid >> 4;       // row group
    const int n0 = blockIdx.x * TM;
    const float* zbase = z + (size_t)(n0 >> 12) * CHW + (n0 & (HW - 1));

    // swizzled read offsets for the two B-granules (involution: g ^ ((g>>3)&1))
    const int g0 = 2 * tx;
    const int g1 = 2 * tx + 1;
    const int p0 = (g0 ^ ((g0 >> 3) & 1)) << 2;
    const int p1 = (g1 ^ ((g1 >> 3) & 1)) << 2;

    float minv[8];
    int   mini[8];
    float rowsq[8];                // per-row ||z||^2 (filled during cc==0)
    #pragma unroll
    for (int i = 0; i < 8; i++) { minv[i] = 3.4e38f; mini[i] = 0; rowsq[i] = 0.f; }

    for (int cc = 0; cc < NE / TN; cc++) {
        const int code0 = cc * TN;
        float acc[8][8];
        #pragma unroll
        for (int i = 0; i < 8; i++)
            #pragma unroll
            for (int j = 0; j < 8; j++) acc[i][j] = 0.f;

        for (int kc = 0; kc < ED / TK; kc++) {
            const int c0 = kc * TK;
            __syncthreads();
            #pragma unroll
            for (int q = 0; q < 4; q++) {
                int u  = tid + q * 256;
                int c  = u >> 5;                 // 0..31 (constant per warp)
                int l  = u & 31;                 // lane
                int l4 = l << 2;
                float4 zv = *(const float4*)(zbase + (size_t)(c0 + c) * HW + l4);
                *(float4*)&zs[c][l4] = zv;
                int gs = (l ^ ((l >> 3) & 1)) << 2;
                float4 ev = *(const float4*)(&g_embT[(c0 + c) * NE + code0 + l4]);
                *(float4*)&es[c][gs] = ev;
            }
            if (kc == 0 && tid < TN) e2s[tid] = g_e2[code0 + tid];
            __syncthreads();

            if (cc == 0) {
                #pragma unroll
                for (int k = 0; k < TK; k++) {
                    float4 a0 = *(const float4*)&zs[k][ty * 8];
                    float4 a1 = *(const float4*)&zs[k][ty * 8 + 4];
                    float4 b0 = *(const float4*)&es[k][p0];
                    float4 b1 = *(const float4*)&es[k][p1];
                    float a[8] = {a0.x, a0.y, a0.z, a0.w, a1.x, a1.y, a1.z, a1.w};
                    float b[8] = {b0.x, b0.y, b0.z, b0.w, b1.x, b1.y, b1.z, b1.w};
                    #pragma unroll
                    for (int i = 0; i < 8; i++) {
                        rowsq[i] += a[i] * a[i];
                        #pragma unroll
                        for (int j = 0; j < 8; j++)
                            acc[i][j] += a[i] * b[j];
                    }
                }
            } else {
                #pragma unroll
                for (int k = 0; k < TK; k++) {
                    float4 a0 = *(const float4*)&zs[k][ty * 8];
                    float4 a1 = *(const float4*)&zs[k][ty * 8 + 4];
                    float4 b0 = *(const float4*)&es[k][p0];
                    float4 b1 = *(const float4*)&es[k][p1];
                    float a[8] = {a0.x, a0.y, a0.z, a0.w, a1.x, a1.y, a1.z, a1.w};
                    float b[8] = {b0.x, b0.y, b0.z, b0.w, b1.x, b1.y, b1.z, b1.w};
                    #pragma unroll
                    for (int i = 0; i < 8; i++)
                        #pragma unroll
                        for (int j = 0; j < 8; j++)
                            acc[i][j] += a[i] * b[j];
                }
            }
        }

        // d = (z2 + e2) - 2*dot, rounded exactly like the reference expression
        #pragma unroll
        for (int i = 0; i < 8; i++) {
            #pragma unroll
            for (int j = 0; j < 8; j++) {
                int code = code0 + tx * 8 + j;
                float t = __fadd_rn(rowsq[i], e2s[tx * 8 + j]);
                float d = __fadd_rn(t, -2.0f * acc[i][j]);
                if (d < minv[i] || (d == minv[i] && code < mini[i])) {
                    minv[i] = d; mini[i] = code;
                }
            }
        }
    }

    // reduce across the 16 tx lanes (half-warp); xor offsets stay in-half
    #pragma unroll
    for (int off = 8; off >= 1; off >>= 1) {
        #pragma unroll
        for (int i = 0; i < 8; i++) {
            float v2 = __shfl_xor_sync(0xffffffffu, minv[i], off);
            int   i2 = __shfl_xor_sync(0xffffffffu, mini[i], off);
            if (v2 < minv[i] || (v2 == minv[i] && i2 < mini[i])) {
                minv[i] = v2; mini[i] = i2;
            }
        }
    }
    if (tx == 0) {
        #pragma unroll
        for (int i = 0; i < 8; i++) {
            int row = n0 + ty * 8 + i;
            g_idx[row] = mini[i];
            atomicAdd(&g_counts[mini[i]], 1);
        }
    }
}

// ---------------- gather z_q (BCHW layout) + loss partials ----------------
__global__ void gather_kernel(const float* __restrict__ z,
                              float* __restrict__ out, int write_out) {
    float s = 0.f;
    const int stride = gridDim.x * blockDim.x;
    for (int u = blockIdx.x * blockDim.x + threadIdx.x; u < (OUTZ / 4); u += stride) {
        int f   = u << 2;
        int b   = f >> 20;              // CHW = 2^20
        int rem = f & (CHW - 1);
        int c   = rem >> 12;            // HW = 2^12
        int hw  = rem & (HW - 1);
        int n   = (b << 12) + hw;       // row index (multiple of 4)
        int4 id = *(const int4*)&g_idx[n];
        const float* er = g_embT + c * NE;   // row c of transposed table
        float4 q;
        q.x = er[id.x]; q.y = er[id.y]; q.z = er[id.z]; q.w = er[id.w];
        float4 zv = *(const float4*)(z + f);
        if (write_out) *(float4*)(out + f) = q;
        float dx = q.x - zv.x, dy = q.y - zv.y, dz = q.z - zv.z, dw = q.w - zv.w;
        s += dx * dx + dy * dy + dz * dz + dw * dw;
    }
    #pragma unroll
    for (int off = 16; off; off >>= 1)
        s += __shfl_xor_sync(0xffffffffu, s, off);
    __shared__ float red[8];
    int t = threadIdx.x;
    if ((t & 31) == 0) red[t >> 5] = s;
    __syncthreads();
    if (t == 0) {
        float bsum = 0.f;
        #pragma unroll
        for (int i = 0; i < 8; i++) bsum += red[i];
        g_partial[blockIdx.x] = bsum;   // deterministic: fixed slot per block
    }
}

// ---------------- final scalars: loss + perplexity ------------------------
__global__ void final_kernel(float* out, int out_size) {
    int t = threadIdx.x;                    // 1024 threads
    double dl = (double)g_partial[t];
    float  em = (float)g_counts[t] * (1.0f / (float)NROWS);
    float  te = em * logf(em + 1e-10f);
    #pragma unroll
    for (int off = 16; off; off >>= 1) {
        dl += __shfl_xor_sync(0xffffffffu, dl, off);
        te += __shfl_xor_sync(0xffffffffu, te, off);
    }
    __shared__ double rD[32];
    __shared__ float  rF[32];
    int w = t >> 5, l = t & 31;
    if (l == 0) { rD[w] = dl; rF[w] = te; }
    __syncthreads();
    if (w == 0) {
        double d2 = rD[l];
        float  f2 = rF[l];
        #pragma unroll
        for (int off = 16; off; off >>= 1) {
            d2 += __shfl_xor_sync(0xffffffffu, d2, off);
            f2 += __shfl_xor_sync(0xffffffffu, f2, off);
        }
        if (l == 0) {
            float loss = (float)(d2 * (1.25 / (double)OUTZ));
            float perp = expf(-f2);
            if (out_size >= OUTZ + 1) out[OUTZ] = loss;
            if (out_size >= OUTZ + 2) out[OUTZ + 1] = perp;
            if (out_size <= 2 && out_size >= 1) out[0] = loss;
            if (out_size == 2) out[1] = perp;
        }
    }
}

// ---------------- idx emission variants -----------------------------------
__global__ void idxf_kernel(float* __restrict__ dst) {
    int n = blockIdx.x * blockDim.x + threadIdx.x;
    if (n < NROWS) dst[n] = (float)g_idx[n];
}
__global__ void idxi_kernel(int* __restrict__ dst) {
    int n = blockIdx.x * blockDim.x + threadIdx.x;
    if (n < NROWS) dst[n] = g_idx[n];
}

// ---------------- launch ---------------------------------------------------
extern "C" void kernel_launch(void* const* d_in, const int* in_sizes, int n_in,
                              void* d_out, int out_size) {
    const float* z   = (const float*)d_in[0];
    const float* emb = (const float*)d_in[1];
    float* out = (float*)d_out;

    init_kernel<<<1, 1024>>>();
    prep_kernel<<<NE, ED>>>(emb);
    argmin_kernel<<<NROWS / TM, 256>>>(z);

    int write_out = (out_size >= OUTZ) ? 1 : 0;
    gather_kernel<<<1024, 256>>>(z, out, write_out);
    final_kernel<<<1, 1024>>>(out, out_size);

    if (out_size >= OUTZ + 2 + NROWS) {
        idxf_kernel<<<(NROWS + 255) / 256, 256>>>(out + OUTZ + 2);
    } else if (out_size == NROWS) {
        idxi_kernel<<<(NROWS + 255) / 256, 256>>>((int*)d_out);
    }
}

// round 9
// speedup vs baseline: 1.9105x; 1.9105x over previous
#include <cuda_runtime.h>
#include <cuda_fp16.h>
#include <cstdint>
#include <math.h>

// Problem constants (fixed by the reference setup_inputs)
#define NE    1024
#define ED    256
#define HW    4096
#define NROWS 65536
#define CHW   (ED * HW)       // 1048576
#define OUTZ  16777216        // 16 * CHW
#define MARGIN 2.0e-4f
#define MAXC  12

// ---------------- scratch (device globals; no allocation allowed) ----------
__device__ __align__(16) float  g_embT[ED * NE];   // [c][code] fp32 (gather)
__device__ float  g_e2[NE];                        // ||e_j||^2
__device__ __align__(16) __half g_B16[NE * ED];    // emb fp16, [code][c]
__device__ float  g_z2[NROWS];                     // per-row ||z||^2 (seq order)
__device__ __align__(16) int  g_cand[NROWS * MAXC];
__device__ int    g_cnt[NROWS];
__device__ __align__(16) int  g_idx[NROWS];
__device__ int    g_counts[NE];
__device__ float  g_partial[1024];

// ======================= helpers ==========================================
__device__ __forceinline__ uint32_t smem_u32(const void* p) {
    uint32_t a;
    asm("{ .reg .u64 t; cvta.to.shared.u64 t, %1; cvt.u32.u64 %0, t; }" : "=r"(a) : "l"(p));
    return a;
}
#define CP_ASYNC16(dst_u32, src) \
    asm volatile("cp.async.cg.shared.global [%0], [%1], 16;" :: "r"(dst_u32), "l"(src))
#define CP_COMMIT() asm volatile("cp.async.commit_group;" ::: "memory")
#define CP_WAIT(n)  asm volatile("cp.async.wait_group %0;" :: "n"(n) : "memory")

__device__ __forceinline__ void mma16816(float d[4], const uint32_t a[4], const uint32_t b[2]) {
    asm volatile(
        "mma.sync.aligned.m16n8k16.row.col.f32.f16.f16.f32 "
        "{%0,%1,%2,%3}, {%4,%5,%6,%7}, {%8,%9}, {%0,%1,%2,%3};"
        : "+f"(d[0]), "+f"(d[1]), "+f"(d[2]), "+f"(d[3])
        : "r"(a[0]), "r"(a[1]), "r"(a[2]), "r"(a[3]), "r"(b[0]), "r"(b[1]));
}

// top-4 insert, ascending value; strict < keeps earliest (lowest) code on ties
__device__ __forceinline__ void ins4(float (&v)[4], int (&ix)[4], float nv, int ni) {
    if (nv < v[3]) {
        if (nv < v[2]) {
            v[3] = v[2]; ix[3] = ix[2];
            if (nv < v[1]) {
                v[2] = v[1]; ix[2] = ix[1];
                if (nv < v[0]) { v[1] = v[0]; ix[1] = ix[0]; v[0] = nv; ix[0] = ni; }
                else           { v[1] = nv; ix[1] = ni; }
            } else { v[2] = nv; ix[2] = ni; }
        } else { v[3] = nv; ix[3] = ni; }
    }
}

// ---------------- smem layout (byte offsets) -------------------------------
#define SM_A    0                         // 128 x 264 half = 67584
#define SM_B    67584                     // 2 bufs x 128 x 144B = 36864
#define SM_SCR  104448                    // scr_v 16K + scr_i 16K
#define SM_E2   137216                    // 1024 f
#define SM_Z2   141312                    // 128 f
#define SMEM_BYTES 141824

// ---------------- init -----------------------------------------------------
__global__ void init_kernel() {
    int t = threadIdx.x;
    if (t < NE) g_counts[t] = 0;
}

// ---------------- prep: transpose + norms + fp16 copy ----------------------
__global__ void prep_kernel(const float* __restrict__ emb) {
    int code = blockIdx.x;      // 0..1023
    int c    = threadIdx.x;     // 0..255
    float v = emb[code * ED + c];
    g_embT[c * NE + code] = v;
    g_B16[code * ED + c] = __float2half_rn(v);
    float s = v * v;
    #pragma unroll
    for (int off = 16; off; off >>= 1)
        s += __shfl_xor_sync(0xffffffffu, s, off);
    __shared__ float red[8];
    if ((c & 31) == 0) red[c >> 5] = s;
    __syncthreads();
    if (c == 0) {
        float t = 0.f;
        #pragma unroll
        for (int i = 0; i < 8; i++) t += red[i];
        g_e2[code] = t;
    }
}

// ---------------- fp16 HMMA coarse GEMM + candidate collection -------------
// CTA: 128 rows x all 1024 codes. 8 warps: m-warp = wid&3 (32 rows),
// n-warp = wid>>2 (64 codes of each 128-code tile). K=256 resident fp16 A.
__global__ __launch_bounds__(256, 1)
void argmin_coarse_kernel(const float* __restrict__ z) {
    extern __shared__ char smem[];
    __half* sAh   = (__half*)(smem + SM_A);
    float*  se2   = (float*)(smem + SM_E2);
    float*  sz2   = (float*)(smem + SM_Z2);
    float*  scr_v = (float*)(smem + SM_SCR);
    int*    scr_i = (int*)(smem + SM_SCR + 16384);
    const uint32_t sB_u = smem_u32(smem + SM_B);

    const int tid  = threadIdx.x;
    const int lane = tid & 31;
    const int g    = lane >> 2;      // groupID (mma row/col base)
    const int t4   = lane & 3;       // threadID in group
    const int wid  = tid >> 5;
    const int mwarp = wid & 3;
    const int nwarp = wid >> 2;
    const int n0  = blockIdx.x * 128;
    const int b   = n0 >> 12;
    const int hw0 = n0 & (HW - 1);

    // e2 table to smem
    #pragma unroll
    for (int i = 0; i < 4; i++) se2[tid + i * 256] = g_e2[tid + i * 256];

    // preload B chunk 0 (code tile 0, k chunk 0)
    {
        const __half* src = g_B16;
        #pragma unroll
        for (int it = 0; it < 4; it++) {
            int u = tid + it * 256;
            int code = u >> 3, seg = u & 7;
            CP_ASYNC16(sB_u + (uint32_t)(code * 144 + seg * 16),
                       src + code * ED + seg * 8);
        }
        CP_COMMIT();
    }

    // ---- A staging + z2 (threads 0..127; row = tid) -----------------------
    if (tid < 128) {
        const float* zrow = z + (size_t)b * CHW + hw0 + tid;
        float z2 = 0.f;
        #pragma unroll 8
        for (int c = 0; c < ED; c++) {
            float v = zrow[(size_t)c * HW];
            z2 += v * v;                        // sequential k order (R3-match)
            sAh[tid * 264 + c] = __float2half_rn(v);
        }
        sz2[tid] = z2;
        g_z2[n0 + tid] = z2;
    }
    __syncthreads();

    float acc[2][8][4];
    #pragma unroll
    for (int mt = 0; mt < 2; mt++)
        #pragma unroll
        for (int nt = 0; nt < 8; nt++)
            #pragma unroll
            for (int e = 0; e < 4; e++) acc[mt][nt][e] = 0.f;

    float tv[4][4]; int tix[4][4];
    #pragma unroll
    for (int s = 0; s < 4; s++)
        #pragma unroll
        for (int e = 0; e < 4; e++) { tv[s][e] = 3.4e38f; tix[s][e] = 0x7fffffff; }

    // ---- 32 chunks: (code tile 0..7) x (k chunk 0..3), double buffered ----
    for (int q = 0; q < 32; q++) {
        const int buf = q & 1;
        if (q < 31) {
            const int qn = q + 1;
            const __half* src = g_B16 + (size_t)((qn >> 2) * 128) * ED + (qn & 3) * 64;
            const uint32_t dst0 = sB_u + (uint32_t)((buf ^ 1) * 18432);
            #pragma unroll
            for (int it = 0; it < 4; it++) {
                int u = tid + it * 256;
                int code = u >> 3, seg = u & 7;
                CP_ASYNC16(dst0 + (uint32_t)(code * 144 + seg * 16),
                           src + code * ED + seg * 8);
            }
            CP_COMMIT();
            CP_WAIT(1);
        } else {
            CP_WAIT(0);
        }
        __syncthreads();

        const __half* sBh = (const __half*)(smem + SM_B + buf * 18432);
        const int kc = q & 3;

        #pragma unroll
        for (int k16 = 0; k16 < 4; k16++) {
            const int kk  = kc * 64 + k16 * 16 + 2 * t4;  // A: global k
            const int kkl = k16 * 16 + 2 * t4;            // B: chunk-local k
            uint32_t afr[2][4];
            #pragma unroll
            for (int mt = 0; mt < 2; mt++) {
                const int r = mwarp * 32 + mt * 16 + g;
                afr[mt][0] = *(const uint32_t*)(sAh + (r)     * 264 + kk);
                afr[mt][1] = *(const uint32_t*)(sAh + (r + 8) * 264 + kk);
                afr[mt][2] = *(const uint32_t*)(sAh + (r)     * 264 + kk + 8);
                afr[mt][3] = *(const uint32_t*)(sAh + (r + 8) * 264 + kk + 8);
            }
            uint32_t bfr[8][2];
            #pragma unroll
            for (int nt = 0; nt < 8; nt++) {
                const int cl = nwarp * 64 + nt * 8 + g;   // local code (B col)
                bfr[nt][0] = *(const uint32_t*)(sBh + cl * 72 + kkl);
                bfr[nt][1] = *(const uint32_t*)(sBh + cl * 72 + kkl + 8);
            }
            #pragma unroll
            for (int mt = 0; mt < 2; mt++)
                #pragma unroll
                for (int nt = 0; nt < 8; nt++)
                    mma16816(acc[mt][nt], afr[mt], bfr[nt]);
        }
        __syncthreads();   // all reads of this buf done before next prefetch

        // ---- per-code-tile epilogue: d = fl(fl(z2+e2) - 2*dot) ------------
        if (kc == 3) {
            const int ct = q >> 2;
            const int cb0 = ct * 128 + nwarp * 64;
            #pragma unroll
            for (int mt = 0; mt < 2; mt++) {
                const int r0 = mwarp * 32 + mt * 16 + g;
                const float z2a = sz2[r0], z2b = sz2[r0 + 8];
                #pragma unroll
                for (int nt = 0; nt < 8; nt++) {
                    const int code = cb0 + nt * 8 + 2 * t4;
                    const float e2a = se2[code], e2b = se2[code + 1];
                    float d00 = __fadd_rn(__fadd_rn(z2a, e2a), -2.0f * acc[mt][nt][0]);
                    float d01 = __fadd_rn(__fadd_rn(z2a, e2b), -2.0f * acc[mt][nt][1]);
                    float d10 = __fadd_rn(__fadd_rn(z2b, e2a), -2.0f * acc[mt][nt][2]);
                    float d11 = __fadd_rn(__fadd_rn(z2b, e2b), -2.0f * acc[mt][nt][3]);
                    ins4(tv[mt * 2 + 0], tix[mt * 2 + 0], d00, code);
                    ins4(tv[mt * 2 + 0], tix[mt * 2 + 0], d01, code + 1);
                    ins4(tv[mt * 2 + 1], tix[mt * 2 + 1], d10, code);
                    ins4(tv[mt * 2 + 1], tix[mt * 2 + 1], d11, code + 1);
                    acc[mt][nt][0] = 0.f; acc[mt][nt][1] = 0.f;
                    acc[mt][nt][2] = 0.f; acc[mt][nt][3] = 0.f;
                }
            }
        }
    }

    // ---- dump per-thread top-4, then per-row candidate selection ----------
    {
        const int eb = (nwarp * 4 + t4) * 4;
        #pragma unroll
        for (int s = 0; s < 4; s++) {
            const int r = mwarp * 32 + (s >> 1) * 16 + g + (s & 1) * 8;
            #pragma unroll
            for (int e = 0; e < 4; e++) {
                scr_v[r * 32 + eb + e] = tv[s][e];
                scr_i[r * 32 + eb + e] = tix[s][e];
            }
        }
    }
    __syncthreads();

    if (tid < 128) {
        const float* rv = scr_v + tid * 32;
        const int*   ri = scr_i + tid * 32;
        float mv = 3.4e38f; int mi = 0x7fffffff;
        #pragma unroll 8
        for (int e = 0; e < 32; e++) {
            float v = rv[e]; int i = ri[e];
            if (v < mv || (v == mv && i < mi)) { mv = v; mi = i; }
        }
        const int n = n0 + tid;
        g_cand[n * MAXC] = mi;
        int cnt = 1;
        const float thr = mv + MARGIN;
        for (int e = 0; e < 32; e++) {
            float v = rv[e]; int i = ri[e];
            if (v <= thr && i != mi && cnt < MAXC) g_cand[n * MAXC + cnt++] = i;
        }
        g_cnt[n] = cnt;
    }
}

// ---------------- exact fp32 re-rank of candidates -------------------------
__global__ void rerank_kernel(const float* __restrict__ z,
                              const float* __restrict__ emb) {
    const int n = blockIdx.x * blockDim.x + threadIdx.x;
    const int C = g_cnt[n];
    int best;
    if (C == 1) {
        best = g_cand[n * MAXC];
    } else {
        int cand[MAXC];
        #pragma unroll
        for (int j = 0; j < MAXC; j++)
            cand[j] = (j < C) ? g_cand[n * MAXC + j] : 0;
        float dot[MAXC];
        #pragma unroll
        for (int j = 0; j < MAXC; j++) dot[j] = 0.f;
        const float* zp = z + (size_t)(n >> 12) * CHW + (n & (HW - 1));
        for (int c4 = 0; c4 < 64; c4++) {
            float z0 = zp[(size_t)(c4 * 4 + 0) * HW];
            float z1 = zp[(size_t)(c4 * 4 + 1) * HW];
            float z2 = zp[(size_t)(c4 * 4 + 2) * HW];
            float z3 = zp[(size_t)(c4 * 4 + 3) * HW];
            #pragma unroll
            for (int j = 0; j < MAXC; j++) {
                if (j < C) {
                    float4 e4 = *(const float4*)(emb + cand[j] * ED + c4 * 4);
                    dot[j] += z0 * e4.x;        // sequential-k FFMA chain,
                    dot[j] += z1 * e4.y;        // identical class to the R3
                    dot[j] += z2 * e4.z;        // kernel that passed
                    dot[j] += z3 * e4.w;
                }
            }
        }
        const float z2r = g_z2[n];
        float bv = 3.4e38f; best = 0x7fffffff;
        #pragma unroll
        for (int j = 0; j < MAXC; j++) {
            if (j < C) {
                int cc = cand[j];
                float t1 = __fadd_rn(z2r, g_e2[cc]);
                float d  = __fadd_rn(t1, -2.0f * dot[j]);
                if (d < bv || (d == bv && cc < best)) { bv = d; best = cc; }
            }
        }
    }
    g_idx[n] = best;
    atomicAdd(&g_counts[best], 1);
}

// ---------------- gather z_q (BCHW) + loss partials ------------------------
__global__ void gather_kernel(const float* __restrict__ z,
                              float* __restrict__ out, int write_out) {
    float s = 0.f;
    const int stride = gridDim.x * blockDim.x;
    for (int u = blockIdx.x * blockDim.x + threadIdx.x; u < (OUTZ / 4); u += stride) {
        int f   = u << 2;
        int b   = f >> 20;
        int rem = f & (CHW - 1);
        int c   = rem >> 12;
        int hw  = rem & (HW - 1);
        int n   = (b << 12) + hw;
        int4 id = *(const int4*)&g_idx[n];
        const float* er = g_embT + c * NE;
        float4 q;
        q.x = er[id.x]; q.y = er[id.y]; q.z = er[id.z]; q.w = er[id.w];
        float4 zv = *(const float4*)(z + f);
        if (write_out) *(float4*)(out + f) = q;
        float dx = q.x - zv.x, dy = q.y - zv.y, dz = q.z - zv.z, dw = q.w - zv.w;
        s += dx * dx + dy * dy + dz * dz + dw * dw;
    }
    #pragma unroll
    for (int off = 16; off; off >>= 1)
        s += __shfl_xor_sync(0xffffffffu, s, off);
    __shared__ float red[8];
    int t = threadIdx.x;
    if ((t & 31) == 0) red[t >> 5] = s;
    __syncthreads();
    if (t == 0) {
        float bsum = 0.f;
        #pragma unroll
        for (int i = 0; i < 8; i++) bsum += red[i];
        g_partial[blockIdx.x] = bsum;
    }
}

// ---------------- final scalars: loss + perplexity -------------------------
__global__ void final_kernel(float* out, int out_size) {
    int t = threadIdx.x;                    // 1024 threads
    double dl = (double)g_partial[t];
    float  em = (float)g_counts[t] * (1.0f / (float)NROWS);
    float  te = em * logf(em + 1e-10f);
    #pragma unroll
    for (int off = 16; off; off >>= 1) {
        dl += __shfl_xor_sync(0xffffffffu, dl, off);
        te += __shfl_xor_sync(0xffffffffu, te, off);
    }
    __shared__ double rD[32];
    __shared__ float  rF[32];
    int w = t >> 5, l = t & 31;
    if (l == 0) { rD[w] = dl; rF[w] = te; }
    __syncthreads();
    if (w == 0) {
        double d2 = rD[l];
        float  f2 = rF[l];
        #pragma unroll
        for (int off = 16; off; off >>= 1) {
            d2 += __shfl_xor_sync(0xffffffffu, d2, off);
            f2 += __shfl_xor_sync(0xffffffffu, f2, off);
        }
        if (l == 0) {
            float loss = (float)(d2 * (1.25 / (double)OUTZ));
            float perp = expf(-f2);
            if (out_size >= OUTZ + 1) out[OUTZ] = loss;
            if (out_size >= OUTZ + 2) out[OUTZ + 1] = perp;
            if (out_size <= 2 && out_size >= 1) out[0] = loss;
            if (out_size == 2) out[1] = perp;
        }
    }
}

// ---------------- idx emission variants ------------------------------------
__global__ void idxf_kernel(float* __restrict__ dst) {
    int n = blockIdx.x * blockDim.x + threadIdx.x;
    if (n < NROWS) dst[n] = (float)g_idx[n];
}
__global__ void idxi_kernel(int* __restrict__ dst) {
    int n = blockIdx.x * blockDim.x + threadIdx.x;
    if (n < NROWS) dst[n] = g_idx[n];
}

// ---------------- launch ---------------------------------------------------
extern "C" void kernel_launch(void* const* d_in, const int* in_sizes, int n_in,
                              void* d_out, int out_size) {
    const float* z   = (const float*)d_in[0];
    const float* emb = (const float*)d_in[1];
    float* out = (float*)d_out;

    cudaFuncSetAttribute(argmin_coarse_kernel,
                         cudaFuncAttributeMaxDynamicSharedMemorySize, SMEM_BYTES);

    init_kernel<<<1, 1024>>>();
    prep_kernel<<<NE, ED>>>(emb);
    argmin_coarse_kernel<<<NROWS / 128, 256, SMEM_BYTES>>>(z);
    rerank_kernel<<<NROWS / 256, 256>>>(z, emb);

    int write_out = (out_size >= OUTZ) ? 1 : 0;
    gather_kernel<<<1024, 256>>>(z, out, write_out);
    final_kernel<<<1, 1024>>>(out, out_size);

    if (out_size >= OUTZ + 2 + NROWS) {
        idxf_kernel<<<(NROWS + 255) / 256, 256>>>(out + OUTZ + 2);
    } else if (out_size == NROWS) {
        idxi_kernel<<<(NROWS + 255) / 256, 256>>>((int*)d_out);
    }
}

// round 10
// speedup vs baseline: 2.3479x; 1.2289x over previous
#include <cuda_runtime.h>
#include <cuda_fp16.h>
#include <cstdint>
#include <math.h>

// Problem constants (fixed by the reference setup_inputs)
#define NE    1024
#define ED    256
#define HW    4096
#define NROWS 65536
#define CHW   (ED * HW)       // 1048576
#define OUTZ  16777216        // 16 * CHW
#define MARGIN 2.0e-4f
#define MAXC  12
#define ROWS  64              // rows per coarse CTA

// ---------------- scratch (device globals; no allocation allowed) ----------
__device__ __align__(16) float  g_embT[ED * NE];   // [c][code] fp32 (gather)
__device__ float  g_e2[NE];                        // ||e_j||^2
__device__ __align__(16) __half g_B16[NE * ED];    // emb fp16, [code][c]
__device__ float  g_z2[NROWS];                     // per-row ||z||^2 (seq order)
__device__ __align__(16) int  g_cand[NROWS * MAXC];
__device__ int    g_cnt[NROWS];
__device__ int    g_wl[NROWS];                     // worklist of C>1 rows
__device__ int    g_wl_cnt;
__device__ __align__(16) int  g_idx[NROWS];
__device__ int    g_counts[NE];
__device__ float  g_partial[1024];

// ======================= helpers ==========================================
__device__ __forceinline__ uint32_t smem_u32(const void* p) {
    uint32_t a;
    asm("{ .reg .u64 t; cvta.to.shared.u64 t, %1; cvt.u32.u64 %0, t; }" : "=r"(a) : "l"(p));
    return a;
}
#define CP_ASYNC16(dst_u32, src) \
    asm volatile("cp.async.cg.shared.global [%0], [%1], 16;" :: "r"(dst_u32), "l"(src))
#define CP_COMMIT() asm volatile("cp.async.commit_group;" ::: "memory")
#define CP_WAIT(n)  asm volatile("cp.async.wait_group %0;" :: "n"(n) : "memory")

__device__ __forceinline__ void mma16816(float d[4], const uint32_t a[4], const uint32_t b[2]) {
    asm volatile(
        "mma.sync.aligned.m16n8k16.row.col.f32.f16.f16.f32 "
        "{%0,%1,%2,%3}, {%4,%5,%6,%7}, {%8,%9}, {%0,%1,%2,%3};"
        : "+f"(d[0]), "+f"(d[1]), "+f"(d[2]), "+f"(d[3])
        : "r"(a[0]), "r"(a[1]), "r"(a[2]), "r"(a[3]), "r"(b[0]), "r"(b[1]));
}

// top-4 insert, ascending value; strict < keeps earliest (lowest) code on ties
__device__ __forceinline__ void ins4(float (&v)[4], int (&ix)[4], float nv, int ni) {
    if (nv < v[3]) {
        if (nv < v[2]) {
            v[3] = v[2]; ix[3] = ix[2];
            if (nv < v[1]) {
                v[2] = v[1]; ix[2] = ix[1];
                if (nv < v[0]) { v[1] = v[0]; ix[1] = ix[0]; v[0] = nv; ix[0] = ni; }
                else           { v[1] = nv; ix[1] = ni; }
            } else { v[2] = nv; ix[2] = ni; }
        } else { v[3] = nv; ix[3] = ni; }
    }
}

// ---------------- smem layout (byte offsets) -------------------------------
#define SM_A    0                          // 64 x 264 half = 33792
#define SM_B    33792                      // 3 stages x 18432 = 55296
#define SM_SCRV SM_B                       // overlay: used only after mainloop
#define SM_SCRI (SM_B + 16384)
#define SM_E2   89088                      // 1024 f
#define SM_Z2   93184                      // 64 f
#define SMEM_BYTES 93440                   // x2 CTAs = 186880 <= 228KB/SM

// ---------------- init -----------------------------------------------------
__global__ void init_kernel() {
    int t = threadIdx.x;
    if (t < NE) g_counts[t] = 0;
    if (t == 0) g_wl_cnt = 0;
}

// ---------------- prep: transpose + norms + fp16 copy ----------------------
__global__ void prep_kernel(const float* __restrict__ emb) {
    int code = blockIdx.x;      // 0..1023
    int c    = threadIdx.x;     // 0..255
    float v = emb[code * ED + c];
    g_embT[c * NE + code] = v;
    g_B16[code * ED + c] = __float2half_rn(v);
    float s = v * v;
    #pragma unroll
    for (int off = 16; off; off >>= 1)
        s += __shfl_xor_sync(0xffffffffu, s, off);
    __shared__ float red[8];
    if ((c & 31) == 0) red[c >> 5] = s;
    __syncthreads();
    if (c == 0) {
        float t = 0.f;
        #pragma unroll
        for (int i = 0; i < 8; i++) t += red[i];
        g_e2[code] = t;
    }
}

// ---------------- fp16 HMMA coarse GEMM + candidate collection -------------
// CTA: 64 rows x all 1024 codes. 8 warps: mwarp = wid&1 (32 rows),
// nwarp = wid>>1 (32 codes of each 128-code tile). 2 CTAs/SM.
// 3-stage cp.async pipeline, ONE __syncthreads per chunk.
__global__ __launch_bounds__(256, 2)
void argmin_coarse_kernel(const float* __restrict__ z) {
    extern __shared__ char smem[];
    __half* sAh   = (__half*)(smem + SM_A);
    float*  se2   = (float*)(smem + SM_E2);
    float*  sz2   = (float*)(smem + SM_Z2);
    float*  scr_v = (float*)(smem + SM_SCRV);
    int*    scr_i = (int*)(smem + SM_SCRI);
    const uint32_t sB_u = smem_u32(smem + SM_B);

    const int tid  = threadIdx.x;
    const int lane = tid & 31;
    const int g    = lane >> 2;      // groupID (mma row/col base)
    const int t4   = lane & 3;       // threadID in group
    const int wid  = tid >> 5;
    const int mwarp = wid & 1;
    const int nwarp = wid >> 1;      // 0..3
    const int n0  = blockIdx.x * ROWS;
    const int b   = n0 >> 12;
    const int hw0 = n0 & (HW - 1);

    // e2 table to smem
    #pragma unroll
    for (int i = 0; i < 4; i++) se2[tid + i * 256] = g_e2[tid + i * 256];

    // prologue: prefetch stages for q=0,1 (overlaps the A staging below)
    #pragma unroll
    for (int s = 0; s < 2; s++) {
        const __half* src = g_B16 + s * 64;          // ct=0, kc=s
        const uint32_t dst0 = sB_u + (uint32_t)(s * 18432);
        #pragma unroll
        for (int it = 0; it < 4; it++) {
            int u = tid + it * 256;
            int code = u >> 3, seg = u & 7;
            CP_ASYNC16(dst0 + (uint32_t)(code * 144 + seg * 16),
                       src + code * ED + seg * 8);
        }
        CP_COMMIT();
    }

    // ---- A staging + z2 (threads 0..63; row = tid; sequential k = R3) -----
    if (tid < ROWS) {
        const float* zrow = z + (size_t)b * CHW + hw0 + tid;
        float z2 = 0.f;
        #pragma unroll 8
        for (int c = 0; c < ED; c++) {
            float v = zrow[(size_t)c * HW];
            z2 += v * v;
            sAh[tid * 264 + c] = __float2half_rn(v);
        }
        sz2[tid] = z2;
        g_z2[n0 + tid] = z2;
    }
    // visibility of sAh/sz2 is covered by the sync inside iteration q=0

    float acc[2][4][4];
    #pragma unroll
    for (int mt = 0; mt < 2; mt++)
        #pragma unroll
        for (int nt = 0; nt < 4; nt++)
            #pragma unroll
            for (int e = 0; e < 4; e++) acc[mt][nt][e] = 0.f;

    float tv[4][4]; int tix[4][4];
    #pragma unroll
    for (int s = 0; s < 4; s++)
        #pragma unroll
        for (int e = 0; e < 4; e++) { tv[s][e] = 3.4e38f; tix[s][e] = 0x7fffffff; }

    // ---- 32 chunks: (code tile ct=q>>2) x (k chunk kc=q&3), 3 stages ------
    for (int q = 0; q < 32; q++) {
        if (q == 31) { CP_WAIT(0); } else { CP_WAIT(1); }
        __syncthreads();                 // stage q visible; q-1 fully consumed
        if (q + 2 < 32) {                // prefetch AFTER the sync (safe overwrite)
            const int qn = q + 2;
            const __half* src = g_B16 + (size_t)((qn >> 2) * 128) * ED + (qn & 3) * 64;
            const uint32_t dst0 = sB_u + (uint32_t)((qn % 3) * 18432);
            #pragma unroll
            for (int it = 0; it < 4; it++) {
                int u = tid + it * 256;
                int code = u >> 3, seg = u & 7;
                CP_ASYNC16(dst0 + (uint32_t)(code * 144 + seg * 16),
                           src + code * ED + seg * 8);
            }
            CP_COMMIT();
        }

        const __half* sBh = (const __half*)(smem + SM_B + (q % 3) * 18432);
        const int kc = q & 3;

        #pragma unroll
        for (int k16 = 0; k16 < 4; k16++) {
            const int kk  = kc * 64 + k16 * 16 + 2 * t4;  // A: global k
            const int kkl = k16 * 16 + 2 * t4;            // B: chunk-local k
            uint32_t afr[2][4];
            #pragma unroll
            for (int mt = 0; mt < 2; mt++) {
                const int r = mwarp * 32 + mt * 16 + g;
                afr[mt][0] = *(const uint32_t*)(sAh + (r)     * 264 + kk);
                afr[mt][1] = *(const uint32_t*)(sAh + (r + 8) * 264 + kk);
                afr[mt][2] = *(const uint32_t*)(sAh + (r)     * 264 + kk + 8);
                afr[mt][3] = *(const uint32_t*)(sAh + (r + 8) * 264 + kk + 8);
            }
            uint32_t bfr[4][2];
            #pragma unroll
            for (int nt = 0; nt < 4; nt++) {
                const int cl = nwarp * 32 + nt * 8 + g;   // local code (B col)
                bfr[nt][0] = *(const uint32_t*)(sBh + cl * 72 + kkl);
                bfr[nt][1] = *(const uint32_t*)(sBh + cl * 72 + kkl + 8);
            }
            #pragma unroll
            for (int mt = 0; mt < 2; mt++)
                #pragma unroll
                for (int nt = 0; nt < 4; nt++)
                    mma16816(acc[mt][nt], afr[mt], bfr[nt]);
        }

        // ---- per-code-tile epilogue: d = fl(fl(z2+e2) - 2*dot) ------------
        if (kc == 3) {
            const int ct = q >> 2;
            const int cb0 = ct * 128 + nwarp * 32;
            #pragma unroll
            for (int mt = 0; mt < 2; mt++) {
                const int r0 = mwarp * 32 + mt * 16 + g;
                const float z2a = sz2[r0], z2b = sz2[r0 + 8];
                #pragma unroll
                for (int nt = 0; nt < 4; nt++) {
                    const int code = cb0 + nt * 8 + 2 * t4;
                    const float e2a = se2[code], e2b = se2[code + 1];
                    float d00 = __fadd_rn(__fadd_rn(z2a, e2a), -2.0f * acc[mt][nt][0]);
                    float d01 = __fadd_rn(__fadd_rn(z2a, e2b), -2.0f * acc[mt][nt][1]);
                    float d10 = __fadd_rn(__fadd_rn(z2b, e2a), -2.0f * acc[mt][nt][2]);
                    float d11 = __fadd_rn(__fadd_rn(z2b, e2b), -2.0f * acc[mt][nt][3]);
                    ins4(tv[mt * 2 + 0], tix[mt * 2 + 0], d00, code);
                    ins4(tv[mt * 2 + 0], tix[mt * 2 + 0], d01, code + 1);
                    ins4(tv[mt * 2 + 1], tix[mt * 2 + 1], d10, code);
                    ins4(tv[mt * 2 + 1], tix[mt * 2 + 1], d11, code + 1);
                    acc[mt][nt][0] = 0.f; acc[mt][nt][1] = 0.f;
                    acc[mt][nt][2] = 0.f; acc[mt][nt][3] = 0.f;
                }
            }
        }
    }

    __syncthreads();   // all B-stage reads done; scratch overlay now safe

    // ---- dump per-thread top-4 (64 entries per row), then select ----------
    {
        const int eb = (nwarp * 4 + t4) * 4;          // 0..60
        #pragma unroll
        for (int s = 0; s < 4; s++) {
            const int r = mwarp * 32 + (s >> 1) * 16 + g + (s & 1) * 8;
            #pragma unroll
            for (int e = 0; e < 4; e++) {
                scr_v[r * 64 + eb + e] = tv[s][e];
                scr_i[r * 64 + eb + e] = tix[s][e];
            }
        }
    }
    __syncthreads();

    if (tid < ROWS) {
        const float* rv = scr_v + tid * 64;
        const int*   ri = scr_i + tid * 64;
        float mv = 3.4e38f; int mi = 0x7fffffff;
        #pragma unroll 8
        for (int e = 0; e < 64; e++) {
            float v = rv[e]; int i = ri[e];
            if (v < mv || (v == mv && i < mi)) { mv = v; mi = i; }
        }
        const int n = n0 + tid;
        g_cand[n * MAXC] = mi;
        int cnt = 1;
        const float thr = mv + MARGIN;
        for (int e = 0; e < 64; e++) {
            float v = rv[e]; int i = ri[e];
            if (v <= thr && i != mi && cnt < MAXC) g_cand[n * MAXC + cnt++] = i;
        }
        if (cnt == 1) {
            g_idx[n] = mi;                     // finalized here; no rerank
            atomicAdd(&g_counts[mi], 1);
        } else {
            g_cnt[n] = cnt;
            int pos = atomicAdd(&g_wl_cnt, 1);
            g_wl[pos] = n;
        }
    }
}

// ---------------- exact fp32 re-rank: one WARP per worklist row ------------
// Lane j computes candidate j's dot with the identical sequential-k fp32
// FFMA chain that passed in R3/R9; warp-reduce (d, code) lexicographic min.
__global__ void rerank_kernel(const float* __restrict__ z,
                              const float* __restrict__ emb) {
    const int lane = threadIdx.x & 31;
    const int gw = (blockIdx.x * blockDim.x + threadIdx.x) >> 5;
    const int nw = (gridDim.x * blockDim.x) >> 5;
    const int wcnt = g_wl_cnt;
    for (int w = gw; w < wcnt; w += nw) {
        const int n = g_wl[w];
        const int C = g_cnt[n];
        const int j = (lane < C) ? lane : (C - 1);
        const int cand = g_cand[n * MAXC + j];
        const float* zp = z + (size_t)(n >> 12) * CHW + (n & (HW - 1));
        const float* ep = emb + cand * ED;
        float dot = 0.f;
        #pragma unroll 4
        for (int c4 = 0; c4 < 64; c4++) {
            float z0 = zp[(size_t)(c4 * 4 + 0) * HW];
            float z1 = zp[(size_t)(c4 * 4 + 1) * HW];
            float z2 = zp[(size_t)(c4 * 4 + 2) * HW];
            float z3 = zp[(size_t)(c4 * 4 + 3) * HW];
            float4 e4 = *(const float4*)(ep + c4 * 4);
            dot += z0 * e4.x;        // sequential-k FFMA chain (R3-identical)
            dot += z1 * e4.y;
            dot += z2 * e4.z;
            dot += z3 * e4.w;
        }
        float t1 = __fadd_rn(g_z2[n], g_e2[cand]);
        float d  = __fadd_rn(t1, -2.0f * dot);
        float bv = (lane < C) ? d : 3.4e38f;
        int   bi = (lane < C) ? cand : 0x7fffffff;
        #pragma unroll
        for (int off = 16; off; off >>= 1) {
            float v2 = __shfl_xor_sync(0xffffffffu, bv, off);
            int   i2 = __shfl_xor_sync(0xffffffffu, bi, off);
            if (v2 < bv || (v2 == bv && i2 < bi)) { bv = v2; bi = i2; }
        }
        if (lane == 0) {
            g_idx[n] = bi;
            atomicAdd(&g_counts[bi], 1);
        }
    }
}

// ---------------- gather z_q (BCHW) + loss partials ------------------------
__global__ void gather_kernel(const float* __restrict__ z,
                              float* __restrict__ out, int write_out) {
    float s = 0.f;
    const int stride = gridDim.x * blockDim.x;
    for (int u = blockIdx.x * blockDim.x + threadIdx.x; u < (OUTZ / 4); u += stride) {
        int f   = u << 2;
        int b   = f >> 20;
        int rem = f & (CHW - 1);
        int c   = rem >> 12;
        int hw  = rem & (HW - 1);
        int n   = (b << 12) + hw;
        int4 id = *(const int4*)&g_idx[n];
        const float* er = g_embT + c * NE;
        float4 q;
        q.x = er[id.x]; q.y = er[id.y]; q.z = er[id.z]; q.w = er[id.w];
        float4 zv = *(const float4*)(z + f);
        if (write_out) *(float4*)(out + f) = q;
        float dx = q.x - zv.x, dy = q.y - zv.y, dz = q.z - zv.z, dw = q.w - zv.w;
        s += dx * dx + dy * dy + dz * dz + dw * dw;
    }
    #pragma unroll
    for (int off = 16; off; off >>= 1)
        s += __shfl_xor_sync(0xffffffffu, s, off);
    __shared__ float red[8];
    int t = threadIdx.x;
    if ((t & 31) == 0) red[t >> 5] = s;
    __syncthreads();
    if (t == 0) {
        float bsum = 0.f;
        #pragma unroll
        for (int i = 0; i < 8; i++) bsum += red[i];
        g_partial[blockIdx.x] = bsum;
    }
}

// ---------------- final scalars: loss + perplexity -------------------------
__global__ void final_kernel(float* out, int out_size) {
    int t = threadIdx.x;                    // 1024 threads
    double dl = (double)g_partial[t];
    float  em = (float)g_counts[t] * (1.0f / (float)NROWS);
    float  te = em * logf(em + 1e-10f);
    #pragma unroll
    for (int off = 16; off; off >>= 1) {
        dl += __shfl_xor_sync(0xffffffffu, dl, off);
        te += __shfl_xor_sync(0xffffffffu, te, off);
    }
    __shared__ double rD[32];
    __shared__ float  rF[32];
    int w = t >> 5, l = t & 31;
    if (l == 0) { rD[w] = dl; rF[w] = te; }
    __syncthreads();
    if (w == 0) {
        double d2 = rD[l];
        float  f2 = rF[l];
        #pragma unroll
        for (int off = 16; off; off >>= 1) {
            d2 += __shfl_xor_sync(0xffffffffu, d2, off);
            f2 += __shfl_xor_sync(0xffffffffu, f2, off);
        }
        if (l == 0) {
            float loss = (float)(d2 * (1.25 / (double)OUTZ));
            float perp = expf(-f2);
            if (out_size >= OUTZ + 1) out[OUTZ] = loss;
            if (out_size >= OUTZ + 2) out[OUTZ + 1] = perp;
            if (out_size <= 2 && out_size >= 1) out[0] = loss;
            if (out_size == 2) out[1] = perp;
        }
    }
}

// ---------------- idx emission variants ------------------------------------
__global__ void idxf_kernel(float* __restrict__ dst) {
    int n = blockIdx.x * blockDim.x + threadIdx.x;
    if (n < NROWS) dst[n] = (float)g_idx[n];
}
__global__ void idxi_kernel(int* __restrict__ dst) {
    int n = blockIdx.x * blockDim.x + threadIdx.x;
    if (n < NROWS) dst[n] = g_idx[n];
}

// ---------------- launch ---------------------------------------------------
extern "C" void kernel_launch(void* const* d_in, const int* in_sizes, int n_in,
                              void* d_out, int out_size) {
    const float* z   = (const float*)d_in[0];
    const float* emb = (const float*)d_in[1];
    float* out = (float*)d_out;

    cudaFuncSetAttribute(argmin_coarse_kernel,
                         cudaFuncAttributeMaxDynamicSharedMemorySize, SMEM_BYTES);

    init_kernel<<<1, 1024>>>();
    prep_kernel<<<NE, ED>>>(emb);
    argmin_coarse_kernel<<<NROWS / ROWS, 256, SMEM_BYTES>>>(z);
    rerank_kernel<<<512, 256>>>(z, emb);

    int write_out = (out_size >= OUTZ) ? 1 : 0;
    gather_kernel<<<1024, 256>>>(z, out, write_out);
    final_kernel<<<1, 1024>>>(out, out_size);

    if (out_size >= OUTZ + 2 + NROWS) {
        idxf_kernel<<<(NROWS + 255) / 256, 256>>>(out + OUTZ + 2);
    } else if (out_size == NROWS) {
        idxi_kernel<<<(NROWS + 255) / 256, 256>>>((int*)d_out);
    }
}